// round 12
// baseline (speedup 1.0000x reference)
#include <cuda_runtime.h>
#include <math.h>

// Router: RMSNorm -> x @ W^T (16384x128x2816) -> softmax -> top-8 (on PROBS,
// lowest-index tie-break) -> renorm -> *per_expert_scale -> dense (16384,128).
//
// R11: 1024-thread CTAs (32 warps, 8/SMSP, occ 50%), 16 outputs/thread,
// <=64 regs. Per-output accumulation chain bit-identical to the passing R10.

#define DM        2816
#define NE        128
#define TK        8
#define BM        128
#define BK        16
#define NTHREADS  1024
#define KIT       (DM / BK)   // 176
#define AST       132         // GEMM smem tile stride (padded)
#define SST       133         // score tile stride (odd -> conflict-free)
#define RMS_EPS   1e-6f
#define FULLMASK  0xffffffffu

typedef unsigned long long u64;

__device__ __forceinline__ u64 pkdup(float v) {
    u64 r; asm("mov.b64 %0, {%1, %1};" : "=l"(r) : "f"(v)); return r;
}
__device__ __forceinline__ float2 upk2(u64 v) {
    float2 r; asm("mov.b64 {%0, %1}, %2;" : "=f"(r.x), "=f"(r.y) : "l"(v)); return r;
}
__device__ __forceinline__ void ffma2(u64& d, u64 a, u64 b) {
    asm("fma.rn.f32x2 %0, %1, %2, %0;" : "+l"(d) : "l"(a), "l"(b));
}
__device__ __forceinline__ void fadd2(u64& d, u64 a) {
    asm("add.rn.f32x2 %0, %0, %1;" : "+l"(d) : "l"(a));
}

// W pre-folded with `scale`, transposed to [K][E]. 1.44 MB, L2-resident.
__device__ float g_wt[DM * NE];

__global__ void fold_kernel(const float* __restrict__ w,
                            const float* __restrict__ scale) {
    __shared__ float t[32][33];
    const int k0 = blockIdx.y * 32, e0 = blockIdx.x * 32;
    const int tx = threadIdx.x, ty = threadIdx.y;      // (32, 8)
    #pragma unroll
    for (int i = 0; i < 4; i++)
        t[ty + 8 * i][tx] = w[(size_t)(e0 + ty + 8 * i) * DM + k0 + tx];
    __syncthreads();
    #pragma unroll
    for (int i = 0; i < 4; i++) {
        const int k = k0 + ty + 8 * i;
        g_wt[(size_t)k * NE + e0 + tx] = t[tx][ty + 8 * i] * scale[k];
    }
}

struct GemmSmem {
    float As[2][BK][AST];   // 16896 B
    float Bs[2][BK][AST];   // 16896 B (total 33792 B)
};
union RouterSmem {
    GemmSmem g;
    float S[64][SST];       // 34048 B (aliases GEMM buffers; used after)
};

__global__ void __launch_bounds__(NTHREADS, 1)
router_kernel(const float* __restrict__ x,
              const float* __restrict__ pes,
              float* __restrict__ out)
{
    __shared__ __align__(16) RouterSmem sm;
    __shared__ float frow[BM];
    __shared__ float pesh[NE];

    const int tid  = threadIdx.x;
    const int tx   = tid & 63;          // 64 col groups x 2 experts
    const int ty   = tid >> 6;          // 16 row groups x 8 tokens (warp-uniform)
    const int r0   = ty * 8;
    const int c0   = tx * 2;
    const int lrow = tid >> 3;          // 0..127 : A load row
    const int kc2  = (tid & 7) * 2;     // 0,2,..,14 : A load k-offset
    const int kb   = tid >> 6;          // 0..15 : B load k-row
    const int cb   = (tid & 63) * 2;    // B load expert-offset

    const size_t rowbase = (size_t)blockIdx.x * BM;
    const float* xa = x + (rowbase + lrow) * DM + kc2;
    const float* wt = g_wt + (size_t)kb * NE + cb;

    if (tid < NE) pesh[tid] = pes[tid];

    u64 acc[4][2];                       // [token-pair][expert]
    #pragma unroll
    for (int i = 0; i < 4; i++) { acc[i][0] = 0ull; acc[i][1] = 0ull; }

    float ss = 0.f;                      // partial sum of squares, row lrow
    float2 ra, rb;

    auto ldg_tile = [&](int kt) {
        ra = *(const float2*)(xa + kt * BK);
        rb = *(const float2*)(wt + (size_t)kt * BK * NE);
    };

    auto sts_tile = [&](int b) {
        ss = fmaf(ra.x, ra.x, ss);
        ss = fmaf(ra.y, ra.y, ss);
        sm.g.As[b][kc2 + 0][lrow] = ra.x;     // transpose to [k][token]
        sm.g.As[b][kc2 + 1][lrow] = ra.y;
        *(float2*)&sm.g.Bs[b][kb][cb] = rb;   // straight-through [k][e]
    };

    // Tile-local accumulation: per-output chain identical to passing kernel.
    auto compute = [&](int b) {
        u64 tacc[4][2];
        #pragma unroll
        for (int i = 0; i < 4; i++) { tacc[i][0] = 0ull; tacc[i][1] = 0ull; }
        #pragma unroll
        for (int kk = 0; kk < BK; kk++) {
            ulonglong2 ap0 = *(const ulonglong2*)&sm.g.As[b][kk][r0];      // bcast
            ulonglong2 ap1 = *(const ulonglong2*)&sm.g.As[b][kk][r0 + 4];  // bcast
            float2 b2 = *(const float2*)&sm.g.Bs[b][kk][c0];
            u64 bd0 = pkdup(b2.x), bd1 = pkdup(b2.y);
            u64 ap[4] = { ap0.x, ap0.y, ap1.x, ap1.y };
            #pragma unroll
            for (int i = 0; i < 4; i++) {
                ffma2(tacc[i][0], ap[i], bd0);
                ffma2(tacc[i][1], ap[i], bd1);
            }
        }
        #pragma unroll
        for (int i = 0; i < 4; i++) {
            fadd2(acc[i][0], tacc[i][0]);
            fadd2(acc[i][1], tacc[i][1]);
        }
    };

    // ---- mainloop: double-buffered, register-staged ----
    ldg_tile(0);
    sts_tile(0);
    __syncthreads();
    int buf = 0;
    for (int kt = 1; kt < KIT; kt++) {
        ldg_tile(kt);
        compute(buf);
        sts_tile(buf ^ 1);
        __syncthreads();
        buf ^= 1;
    }
    compute(buf);
    __syncthreads();   // GEMM buffers dead -> safe to alias with S

    // ---- RMSNorm factor per row (8 loader threads per row) ----
    ss += __shfl_xor_sync(FULLMASK, ss, 1);
    ss += __shfl_xor_sync(FULLMASK, ss, 2);
    ss += __shfl_xor_sync(FULLMASK, ss, 4);
    const float kInvSqrtD = (float)(1.0 / sqrt((double)DM));
    if ((tid & 7) == 0)
        frow[lrow] = (1.0f / sqrtf(ss * (1.0f / DM) + RMS_EPS)) * kInvSqrtD;
    __syncthreads();

    const int wid  = tid >> 5;
    const int lane = tid & 31;

    // ---- epilogue: 2 phases of 64 tokens ----
    #pragma unroll
    for (int ph = 0; ph < 2; ph++) {
        if ((ty >> 3) == ph) {
            const int rr = r0 - ph * 64;
            #pragma unroll
            for (int i = 0; i < 4; i++) {
                const int t0 = 2 * i;
                float f0 = frow[r0 + t0], f1 = frow[r0 + t0 + 1];
                #pragma unroll
                for (int j = 0; j < 2; j++) {
                    float2 v = upk2(acc[i][j]);
                    sm.S[rr + t0][c0 + j]     = v.x * f0;
                    sm.S[rr + t0 + 1][c0 + j] = v.y * f1;
                }
            }
        }
        __syncthreads();

        // warp-per-token selection: 32 warps x 2 iterations = 64 rows
        for (int it = 0; it < 2; it++) {
            const int lrowS = it * 32 + wid;
            float sv[4];
            int   pi[4];
            #pragma unroll
            for (int q = 0; q < 4; q++) {
                pi[q] = lane + 32 * q;
                sv[q] = sm.S[lrowS][pi[q]];
            }
            // exact row max
            float m = fmaxf(fmaxf(sv[0], sv[1]), fmaxf(sv[2], sv[3]));
            #pragma unroll
            for (int off = 16; off >= 1; off >>= 1)
                m = fmaxf(m, __shfl_xor_sync(FULLMASK, m, off));
            // softmax numerators (libdevice expf, matching XLA)
            float ev[4];
            #pragma unroll
            for (int q = 0; q < 4; q++) ev[q] = expf(sv[q] - m);
            // Z: strided partials + shfl-down tree
            float z = ((ev[0] + ev[1]) + ev[2]) + ev[3];
            #pragma unroll
            for (int off = 16; off >= 1; off >>= 1)
                z += __shfl_down_sync(FULLMASK, z, off);
            z = __shfl_sync(FULLMASK, z, 0);
            // probs via IEEE division — quantization makes the ties TopK
            // breaks by LOWEST index.
            float pv[4];
            #pragma unroll
            for (int q = 0; q < 4; q++) pv[q] = __fdiv_rn(ev[q], z);

            // top-8 on probs, lexicographic (p desc, idx asc) argmax x8
            float wv[TK]; int wi[TK];
            #pragma unroll
            for (int r = 0; r < TK; r++) {
                float bv = pv[0]; int bidx = pi[0];
                #pragma unroll
                for (int q = 1; q < 4; q++)
                    if (pv[q] > bv || (pv[q] == bv && pi[q] < bidx)) { bv = pv[q]; bidx = pi[q]; }
                #pragma unroll
                for (int off = 16; off >= 1; off >>= 1) {
                    float ov = __shfl_xor_sync(FULLMASK, bv, off);
                    int   oi = __shfl_xor_sync(FULLMASK, bidx, off);
                    if (ov > bv || (ov == bv && oi < bidx)) { bv = ov; bidx = oi; }
                }
                wv[r] = bv; wi[r] = bidx;
                #pragma unroll
                for (int q = 0; q < 4; q++)
                    if (pi[q] == bidx) pv[q] = -1e30f;
            }

            float sumw = wv[0];
            #pragma unroll
            for (int r = 1; r < TK; r++) sumw += wv[r];

            // dense scatter straight to gmem (coalesced 128B rows)
            float* op = out + (rowbase + (size_t)ph * 64 + lrowS) * NE;
            #pragma unroll
            for (int q = 0; q < 4; q++) {
                const int col = pi[q];
                float val = 0.f;
                #pragma unroll
                for (int r = 0; r < TK; r++)
                    if (wi[r] == col) val = __fdiv_rn(wv[r], sumw) * pesh[col];
                op[col] = val;
            }
        }
        __syncthreads();
    }
}

extern "C" void kernel_launch(void* const* d_in, const int* in_sizes, int n_in,
                              void* d_out, int out_size) {
    (void)n_in; (void)out_size;
    const float* x     = (const float*)d_in[0];   // (4,4096,2816) f32
    const float* w     = (const float*)d_in[1];   // (128,2816)    f32
    const float* scale = (const float*)d_in[2];   // (2816,)       f32
    const float* pes   = (const float*)d_in[3];   // (128,)        f32
    float* out = (float*)d_out;                   // (4,4096,128)  f32

    dim3 fgrid(NE / 32, DM / 32);
    fold_kernel<<<fgrid, dim3(32, 8)>>>(w, scale);

    const int tokens = in_sizes[0] / DM;          // 16384
    router_kernel<<<tokens / BM, NTHREADS>>>(x, pes, out);
}